// round 6
// baseline (speedup 1.0000x reference)
#include <cuda_runtime.h>

// RankCoxHazardLoss — B=512 rows, N=256. Sort-based, 512 threads/row:
// thread (k,h) owns sorted slot k=tid&255 and loop-half h=tid>>8.
// den = suffix scan, num_pairs = C(vcnt,2), pass2 over suffix only,
// rank-violations over prefix only. Last CTA reduces to the scalar.

#define EPSF 1e-7f
static constexpr int BB  = 512;
static constexpr int NN  = 256;
static constexpr int TPB = 512;

__device__ float g_row_cox[BB];
__device__ float g_row_vb[BB];
__device__ float g_row_rank[BB];
__device__ unsigned int g_done = 0;

__global__ __launch_bounds__(TPB) void fused_kernel(
    const float* __restrict__ pred,
    const float* __restrict__ target,
    const void*  __restrict__ validp,
    float*       __restrict__ out)
{
    __shared__ unsigned int s_key[NN];
    __shared__ float s_e2[NN];    // exp(pred), sorted
    __shared__ float s_rz[NN];    // valid ? exp(-pred) : 0, sorted
    __shared__ float s_t2[NN];    // masked time, sorted
    __shared__ float s_p2[NN];    // pred, sorted
    __shared__ int   s_rcnt[TPB]; // partial rank counts
    __shared__ float s_rs[TPB];   // partial violation sums
    __shared__ float s_pd[TPB];   // partial survival products
    __shared__ float s_w0[8];     // scan warp totals
    __shared__ float s_r0[16], s_r1[16];
    __shared__ int   s_vc[8];
    __shared__ unsigned int s_islast;

    const int tid  = threadIdx.x;
    const int i    = tid & (NN - 1);   // item / sorted slot
    const int h    = tid >> 8;         // loop half
    const int lane = tid & 31;
    const int wid  = tid >> 5;
    const int sw   = wid & 7;          // slot-warp (0..7)
    const int b    = blockIdx.x;
    const int idx  = b * NN + i;

    // ---- valid_mask dtype detection (bit patterns of first 512 words) ----
    const unsigned int w = ((const unsigned int*)validp)[tid];
    const int any_bf = __syncthreads_or((w == 0x3F803F80u) || (w == 0x00003F80u));
    const int any_f  = __syncthreads_or(w == 0x3F800000u);
    const int any_mb = __syncthreads_or((w & 0xFFFFFF00u) != 0u &&
                                        w != 0x3F800000u && w != 0x3F803F80u &&
                                        w != 0x00003F80u);
    bool v_i;
    if (any_bf)      v_i = ((const unsigned short*)validp)[idx] != 0;
    else if (any_f)  v_i = ((const float*)validp)[idx] != 0.0f;
    else if (any_mb) v_i = ((const unsigned char*)validp)[idx] != 0;
    else             v_i = ((const int*)validp)[idx] != 0;

    const float p_i  = pred[idx];
    const float t_i  = target[idx];
    const float tm_i = v_i ? t_i : -1.0f;

    // unique sortable key: ordered float bits, low 8 bits = item index
    unsigned int u = __float_as_uint(tm_i);
    u ^= (unsigned int)((int)u >> 31) | 0x80000000u;
    const unsigned int key = (u & 0xFFFFFF00u) | (unsigned int)i;

    // one MUFU per thread; h=0 owns key store + ballot
    float myexp;
    if (h == 0) {
        s_key[i] = key;
        myexp = __expf(p_i);
        const unsigned int bal = __ballot_sync(0xffffffffu, v_i);
        if (lane == 0) s_vc[sw] = __popc(bal);
    } else {
        myexp = __expf(-p_i);
    }
    __syncthreads();

    int vcnt = 0;
    #pragma unroll
    for (int k2 = 0; k2 < 8; k2++) vcnt += s_vc[k2];
    const int ninv = NN - vcnt;

    // ---- rank: each h counts its half of the keys ----
    const uint4* k4 = (const uint4*)s_key;
    int rc = 0;
    #pragma unroll 8
    for (int q = 32 * h; q < 32 * h + 32; q++) {
        const uint4 kk = k4[q];
        rc += (kk.x < key) + (kk.y < key) + (kk.z < key) + (kk.w < key);
    }
    s_rcnt[tid] = rc;
    __syncthreads();
    const int rank = s_rcnt[i] + s_rcnt[i + NN];

    // ---- scatter to sorted order (split across h) ----
    if (h == 0) { s_e2[rank] = myexp; s_t2[rank] = tm_i; }
    else        { s_rz[rank] = v_i ? myexp : 0.0f; s_p2[rank] = p_i; }
    __syncthreads();

    const int  k   = i;          // sorted slot owned by this thread
    const float E_k = s_e2[k];

    // ---- den_k = suffix sum of E over [k, 255] (both halves redundant) ----
    float sfx = E_k;
    #pragma unroll
    for (int o = 1; o < 32; o <<= 1) {
        const float t = __shfl_down_sync(0xffffffffu, sfx, o);
        if (lane + o < 32) sfx += t;
    }
    if (lane == 0) s_w0[sw] = sfx;     // both halves write identical values
    __syncthreads();
    float den = sfx;
    #pragma unroll
    for (int k2 = 7; k2 > 0; k2--) if (k2 > sw) den += s_w0[k2];
    const float invden = 1.0f / den;

    // ---- rank violations over prefix [0,k): quads interleaved by h ----
    const float4* e4 = (const float4*)s_e2;
    const float4* z4 = (const float4*)s_rz;
    float rs = 0.0f;
    const int qhi = 8 * (sw + 1);      // warp-uniform prefix bound
    #pragma unroll 4
    for (int q = h; q < qhi; q += 2) {
        const float4 E = e4[q];
        const float4 Z = z4[q];
        const int j = 4 * q;
        if (j + 0 < k && E.x < E_k) rs += Z.x;
        if (j + 1 < k && E.y < E_k) rs += Z.y;
        if (j + 2 < k && E.z < E_k) rs += Z.z;
        if (j + 3 < k && E.w < E_k) rs += Z.w;
    }

    // ---- pass 2 over suffix [k,255] (includes j==k, divided out later) ----
    const float c1c = 1.0f + EPSF;
    const float c2c = 2.0f * EPSF;
    float pd0 = 1.0f, pd1 = 1.0f;
    #pragma unroll 4
    for (int q = 8 * sw + h; q < NN / 4; q += 2) {
        const float4 E = e4[q];
        const int j = 4 * q;
        const float t0 = fmaxf(fmaf(-E.x, invden, c1c), c2c);
        const float t1 = fmaxf(fmaf(-E.y, invden, c1c), c2c);
        const float t2 = fmaxf(fmaf(-E.z, invden, c1c), c2c);
        const float t3 = fmaxf(fmaf(-E.w, invden, c1c), c2c);
        if (j + 0 >= k) pd0 *= t0;
        if (j + 1 >= k) pd1 *= t1;
        if (j + 2 >= k) pd0 *= t2;
        if (j + 3 >= k) pd1 *= t3;
    }
    s_rs[tid] = rs;
    s_pd[tid] = pd0 * pd1;
    __syncthreads();

    // ---- finalize per sorted slot (h=0) ----
    float loss = 0.0f, rankc = 0.0f;
    if (h == 0) {
        const float T_k = s_t2[k];
        const float P_k = s_p2[k];
        const float bmax = s_t2[NN - 1];
        const bool valid_k = (k >= ninv);
        const bool elim = valid_k && (T_k > 0.0f) && (T_k < bmax);
        if (elim) {
            const float prod = s_pd[k] * s_pd[k + NN];
            const float own  = fmaxf(fmaf(-E_k, invden, c1c), c2c); // j==k
            loss = (__logf(den) - P_k) - __logf(prod) + __logf(own);
        }
        if (valid_k) rankc = E_k * (s_rs[k] + s_rs[k + NN]);
    }

    // ---- block reduce (loss, rankc) over 512 threads ----
    #pragma unroll
    for (int o = 16; o; o >>= 1) {
        loss  += __shfl_xor_sync(0xffffffffu, loss, o);
        rankc += __shfl_xor_sync(0xffffffffu, rankc, o);
    }
    if (lane == 0) { s_r0[wid] = loss; s_r1[wid] = rankc; }
    __syncthreads();
    if (tid == 0) {
        float tl = 0.0f, tr = 0.0f;
        #pragma unroll
        for (int k2 = 0; k2 < 16; k2++) { tl += s_r0[k2]; tr += s_r1[k2]; }
        const float fv = (float)vcnt;
        const float npairs = 0.5f * fv * (fv - 1.0f);   // C(vcnt,2)
        const float vb = (vcnt >= 2) ? 1.0f : 0.0f;
        g_row_cox[b]  = vb * tl;
        g_row_vb[b]   = vb;
        g_row_rank[b] = tr / fmaxf(npairs, 1.0f);
        __threadfence();
        const unsigned int t = atomicAdd(&g_done, 1u);
        s_islast = (t == (unsigned int)(BB - 1)) ? 1u : 0u;
    }
    __syncthreads();

    // ---- last block: final scalar reduction over the 512 rows ----
    if (s_islast) {
        float c = g_row_cox[tid];
        float v = g_row_vb[tid];
        float r = g_row_rank[tid];
        #pragma unroll
        for (int o = 16; o; o >>= 1) {
            c += __shfl_xor_sync(0xffffffffu, c, o);
            v += __shfl_xor_sync(0xffffffffu, v, o);
            r += __shfl_xor_sync(0xffffffffu, r, o);
        }
        if (lane == 0) { s_r0[wid] = c; s_r1[wid] = v; ((float*)s_rcnt)[wid] = r; }
        __syncthreads();
        if (tid == 0) {
            float C = 0.0f, V = 0.0f, R = 0.0f;
            #pragma unroll
            for (int k2 = 0; k2 < 16; k2++) {
                C += s_r0[k2]; V += s_r1[k2]; R += ((float*)s_rcnt)[k2];
            }
            out[0] = C / fmaxf(V, 1.0f) + R * (1.0f / (float)BB);
            g_done = 0;   // reset for next graph replay
        }
    }
}

extern "C" void kernel_launch(void* const* d_in, const int* in_sizes, int n_in,
                              void* d_out, int out_size)
{
    const float* pred   = (const float*)d_in[0];
    const float* target = (const float*)d_in[1];
    const void*  valid  = (const void*)d_in[2];
    float*       out    = (float*)d_out;

    fused_kernel<<<BB, TPB>>>(pred, target, valid, out);
}

// round 7
// speedup vs baseline: 1.3764x; 1.3764x over previous
#include <cuda_runtime.h>

// RankCoxHazardLoss — B=512 rows, N=256. Sort-based, 256 thr/row (single wave).
// den = suffix scan; num_pairs = C(vcnt,2); pass2 (survival product) over the
// strict suffix j>k with packed f32x2 FMA/MUL; rank violations over prefix j<k.
// Last CTA reduces the per-row partials to the scalar.

#define EPSF 1e-7f
static constexpr int BB = 512;
static constexpr int NN = 256;

__device__ float g_row_cox[BB];
__device__ float g_row_vb[BB];
__device__ float g_row_rank[BB];
__device__ unsigned int g_done = 0;

__device__ __forceinline__ unsigned long long pack2(float a, float b) {
    unsigned long long r;
    asm("mov.b64 %0, {%1, %2};" : "=l"(r) : "f"(a), "f"(b));
    return r;
}
__device__ __forceinline__ unsigned long long fma2(
    unsigned long long a, unsigned long long b, unsigned long long c) {
    unsigned long long d;
    asm("fma.rn.f32x2 %0, %1, %2, %3;" : "=l"(d) : "l"(a), "l"(b), "l"(c));
    return d;
}
__device__ __forceinline__ unsigned long long mul2(
    unsigned long long a, unsigned long long b) {
    unsigned long long d;
    asm("mul.rn.f32x2 %0, %1, %2;" : "=l"(d) : "l"(a), "l"(b));
    return d;
}
__device__ __forceinline__ void unpack2(unsigned long long v, float& lo, float& hi) {
    asm("mov.b64 {%0, %1}, %2;" : "=f"(lo), "=f"(hi) : "l"(v));
}

__global__ __launch_bounds__(NN) void fused_kernel(
    const float* __restrict__ pred,
    const float* __restrict__ target,
    const void*  __restrict__ validp,
    float*       __restrict__ out)
{
    __shared__ __align__(16) unsigned int s_key[NN];
    __shared__ __align__(16) float s_e2[NN];   // exp(pred), sorted
    __shared__ __align__(16) float s_rz[NN];   // valid ? exp(-pred) : 0, sorted
    __shared__ __align__(16) float s_t2[NN];   // masked time, sorted
    __shared__ float s_w0[8], s_w1[8];
    __shared__ int   s_vc[8];
    __shared__ unsigned int s_islast;

    const int tid  = threadIdx.x;
    const int lane = tid & 31;
    const int wid  = tid >> 5;
    const int b    = blockIdx.x;
    const int idx  = b * NN + tid;

    // ---- valid_mask dtype detection (bit patterns of first 256 words) ----
    const unsigned int w = ((const unsigned int*)validp)[tid];
    const int any_bf = __syncthreads_or((w == 0x3F803F80u) || (w == 0x00003F80u));
    const int any_f  = __syncthreads_or(w == 0x3F800000u);
    const int any_mb = __syncthreads_or((w & 0xFFFFFF00u) != 0u &&
                                        w != 0x3F800000u && w != 0x3F803F80u &&
                                        w != 0x00003F80u);
    bool v_i;
    if (any_bf)      v_i = ((const unsigned short*)validp)[idx] != 0;
    else if (any_f)  v_i = ((const float*)validp)[idx] != 0.0f;
    else if (any_mb) v_i = ((const unsigned char*)validp)[idx] != 0;
    else             v_i = ((const int*)validp)[idx] != 0;

    const float p_i  = pred[idx];
    const float t_i  = target[idx];
    const float tm_i = v_i ? t_i : -1.0f;

    // unique sortable key: ordered float bits, low 8 bits = index
    unsigned int u = __float_as_uint(tm_i);
    u ^= (unsigned int)((int)u >> 31) | 0x80000000u;
    const unsigned int key = (u & 0xFFFFFF00u) | (unsigned int)tid;
    s_key[tid] = key;

    const unsigned int bal = __ballot_sync(0xffffffffu, v_i);
    if (lane == 0) s_vc[wid] = __popc(bal);
    __syncthreads();
    int vcnt = 0;
    #pragma unroll
    for (int k2 = 0; k2 < 8; k2++) vcnt += s_vc[k2];
    const int ninv = NN - vcnt;

    // ---- rank = #{key_j < key_i} ----
    const uint4* k4 = (const uint4*)s_key;
    int r0 = 0, r1 = 0;
    #pragma unroll 8
    for (int q = 0; q < NN / 4; q++) {
        const uint4 kk = k4[q];
        r0 += (kk.x < key); r1 += (kk.y < key);
        r0 += (kk.z < key); r1 += (kk.w < key);
    }
    const int rank = r0 + r1;

    // ---- scatter to sorted order ----
    s_e2[rank] = __expf(p_i);
    s_rz[rank] = v_i ? __expf(-p_i) : 0.0f;
    s_t2[rank] = tm_i;
    __syncthreads();

    const int   k   = tid;            // sorted slot owned by this thread
    const float E_k = s_e2[k];
    const float T_k = s_t2[k];
    const float bmax = s_t2[NN - 1];

    // ---- den_k = suffix sum of E over [k, 255] ----
    float sfx = E_k;
    #pragma unroll
    for (int o = 1; o < 32; o <<= 1) {
        const float t = __shfl_down_sync(0xffffffffu, sfx, o);
        if (lane + o < 32) sfx += t;
    }
    if (lane == 0) s_w0[wid] = sfx;
    __syncthreads();
    float den = sfx;
    #pragma unroll
    for (int k2 = 7; k2 > 0; k2--) if (k2 > wid) den += s_w0[k2];
    const float invden = 1.0f / den;

    const int qb = k >> 2;       // boundary quad index
    const int kc = k & 3;        // position within boundary quad

    // ---- rank violations over prefix j<k: full quads [0,qb), then boundary ----
    const float4* e4 = (const float4*)s_e2;
    const float4* z4 = (const float4*)s_rz;
    float rs = 0.0f;
    #pragma unroll 4
    for (int q = 0; q < qb; q++) {
        const float4 E = e4[q];
        const float4 Z = z4[q];
        if (E.x < E_k) rs += Z.x;
        if (E.y < E_k) rs += Z.y;
        if (E.z < E_k) rs += Z.z;
        if (E.w < E_k) rs += Z.w;
    }
    {   // boundary quad: pairs j = 4*qb + c with c < kc
        const float4 E = e4[qb];
        const float4 Z = z4[qb];
        if (0 < kc && E.x < E_k) rs += Z.x;
        if (1 < kc && E.y < E_k) rs += Z.y;
        if (2 < kc && E.z < E_k) rs += Z.z;
        if (3 < kc && E.w < E_k) rs += Z.w;
    }

    // ---- pass 2: survival product over strict suffix j>k ----
    // term_j = (1+eps) - E_j/den_k  (clamp provably never fires for j>k)
    const float c1c = 1.0f + EPSF;
    float pdx = 1.0f;
    {   // boundary quad: pairs j = 4*qb + c with c > kc
        const float4 E = e4[qb];
        if (0 > kc) pdx *= fmaf(-E.x, invden, c1c);
        if (1 > kc) pdx *= fmaf(-E.y, invden, c1c);
        if (2 > kc) pdx *= fmaf(-E.z, invden, c1c);
        if (3 > kc) pdx *= fmaf(-E.w, invden, c1c);
    }
    const unsigned long long ninv2 = pack2(-invden, -invden);
    const unsigned long long c1c2  = pack2(c1c, c1c);
    unsigned long long pdA = pack2(1.0f, 1.0f);
    unsigned long long pdB = pdA;
    const ulonglong2* e8 = (const ulonglong2*)s_e2;
    #pragma unroll 4
    for (int q = qb + 1; q < NN / 4; q++) {
        const ulonglong2 E2 = e8[q];
        pdA = mul2(pdA, fma2(E2.x, ninv2, c1c2));
        pdB = mul2(pdB, fma2(E2.y, ninv2, c1c2));
    }
    float a0, a1, b0, b1;
    unpack2(pdA, a0, a1);
    unpack2(pdB, b0, b1);
    const float prod = pdx * ((a0 * a1) * (b0 * b1));

    // ---- finalize per sorted slot ----
    const bool valid_k = (k >= ninv);
    const bool elim = valid_k && (T_k > 0.0f) && (T_k < bmax);
    float loss = 0.0f;
    if (elim)
        loss = (__logf(den) - __logf(E_k)) - __logf(prod);
    float rankc = valid_k ? E_k * rs : 0.0f;

    // ---- block reduce (loss, rankc) ----
    #pragma unroll
    for (int o = 16; o; o >>= 1) {
        loss  += __shfl_xor_sync(0xffffffffu, loss, o);
        rankc += __shfl_xor_sync(0xffffffffu, rankc, o);
    }
    __syncthreads();                       // s_w0 reuse
    if (lane == 0) { s_w0[wid] = loss; s_w1[wid] = rankc; }
    __syncthreads();
    if (tid == 0) {
        float tl = 0.0f, tr = 0.0f;
        #pragma unroll
        for (int k2 = 0; k2 < 8; k2++) { tl += s_w0[k2]; tr += s_w1[k2]; }
        const float fv = (float)vcnt;
        const float npairs = 0.5f * fv * (fv - 1.0f);   // C(vcnt,2)
        const float vb = (vcnt >= 2) ? 1.0f : 0.0f;
        g_row_cox[b]  = vb * tl;
        g_row_vb[b]   = vb;
        g_row_rank[b] = tr / fmaxf(npairs, 1.0f);
        __threadfence();
        const unsigned int t = atomicAdd(&g_done, 1u);
        s_islast = (t == (unsigned int)(BB - 1)) ? 1u : 0u;
    }
    __syncthreads();

    // ---- last block: final scalar reduction over 512 rows ----
    if (s_islast) {
        float c = g_row_cox[tid]  + g_row_cox[tid + NN];
        float v = g_row_vb[tid]   + g_row_vb[tid + NN];
        float r = g_row_rank[tid] + g_row_rank[tid + NN];
        #pragma unroll
        for (int o = 16; o; o >>= 1) {
            c += __shfl_xor_sync(0xffffffffu, c, o);
            v += __shfl_xor_sync(0xffffffffu, v, o);
            r += __shfl_xor_sync(0xffffffffu, r, o);
        }
        __syncthreads();
        if (lane == 0) { s_w0[wid] = c; s_w1[wid] = v; ((float*)s_vc)[wid] = r; }
        __syncthreads();
        if (tid == 0) {
            float C = 0.0f, V = 0.0f, R = 0.0f;
            #pragma unroll
            for (int k2 = 0; k2 < 8; k2++) {
                C += s_w0[k2]; V += s_w1[k2]; R += ((float*)s_vc)[k2];
            }
            out[0] = C / fmaxf(V, 1.0f) + R * (1.0f / (float)BB);
            g_done = 0;   // reset for next graph replay
        }
    }
}

extern "C" void kernel_launch(void* const* d_in, const int* in_sizes, int n_in,
                              void* d_out, int out_size)
{
    const float* pred   = (const float*)d_in[0];
    const float* target = (const float*)d_in[1];
    const void*  valid  = (const void*)d_in[2];
    float*       out    = (float*)d_out;

    fused_kernel<<<BB, NN>>>(pred, target, valid, out);
}